// round 1
// baseline (speedup 1.0000x reference)
#include <cuda_runtime.h>
#include <math.h>

#define Bb 2
#define Tt 1024
#define Cc 2048
#define Hh 32
#define Dd 64
#define BT (Bb*Tt)
#define BTC (BT*Cc)
#define NEG_INF (-1e30f)

// ---------------- scratch (device globals; no allocation) ----------------
__device__ float s_dx[BTC];
__device__ float s_xxx[BTC];
__device__ float s_h[BT*96];
__device__ float s_xq[BTC];
__device__ float s_xk[BTC];
__device__ float s_xv[BTC];
__device__ float s_rq[BTC];
__device__ float s_rk[BTC];
__device__ float s_rv[BTC];
__device__ float s_q[BTC];   // (B,H,T,D)
__device__ float s_k[BTC];   // (B,H,T,D)
__device__ float s_v[BTC];   // (B,H,T,D)
__device__ float s_o[BTC];   // (B,T,C)
__device__ float s_oln[BTC];

// ---------------- K1: token shift + xxx ----------------
__global__ __launch_bounds__(256) void k_shift(const float* __restrict__ x,
                                               const float* __restrict__ shift,
                                               const float* __restrict__ tmx) {
    int i = blockIdx.x * 256 + threadIdx.x;
    int c = i & (Cc - 1);
    int bt = i >> 11;
    int t = bt & (Tt - 1);
    int b = bt >> 10;
    float xv = x[i];
    float xp = (t == 0) ? shift[b * Cc + c] : x[i - Cc];
    float dx = xp - xv;
    s_dx[i] = dx;
    s_xxx[i] = xv + dx * tmx[c];
}

// ---------------- K2: h = tanh(xxx @ w1), w1 is (C,96) ----------------
__global__ __launch_bounds__(96) void k_lora1(const float* __restrict__ w1) {
    __shared__ float sx[4][Cc];
    int r0 = blockIdx.x * 4;
    for (int i = threadIdx.x; i < 4 * Cc; i += 96) {
        sx[i >> 11][i & (Cc - 1)] = s_xxx[r0 * Cc + i];
    }
    __syncthreads();
    int j = threadIdx.x;  // 0..95
    float a0 = 0.f, a1 = 0.f, a2 = 0.f, a3 = 0.f;
    for (int c = 0; c < Cc; c++) {
        float w = w1[c * 96 + j];
        a0 += sx[0][c] * w;
        a1 += sx[1][c] * w;
        a2 += sx[2][c] * w;
        a3 += sx[3][c] * w;
    }
    s_h[(r0 + 0) * 96 + j] = tanhf(a0);
    s_h[(r0 + 1) * 96 + j] = tanhf(a1);
    s_h[(r0 + 2) * 96 + j] = tanhf(a2);
    s_h[(r0 + 3) * 96 + j] = tanhf(a3);
}

// ---------------- K3: m = h @ w2 (per l), then xq/xk/xv mix ----------------
__global__ __launch_bounds__(256) void k_mix(const float* __restrict__ x,
                                             const float* __restrict__ tmr,
                                             const float* __restrict__ tmk,
                                             const float* __restrict__ tmv,
                                             const float* __restrict__ w2) {
    __shared__ float sh[4][96];
    int r0 = blockIdx.x * 4;
    for (int i = threadIdx.x; i < 4 * 96; i += 256) {
        sh[i / 96][i % 96] = s_h[r0 * 96 + i];
    }
    __syncthreads();
    for (int c = threadIdx.x; c < Cc; c += 256) {
        float mr[4] = {0.f, 0.f, 0.f, 0.f};
        float mk[4] = {0.f, 0.f, 0.f, 0.f};
        float mv[4] = {0.f, 0.f, 0.f, 0.f};
#pragma unroll 8
        for (int i = 0; i < 32; i++) {
            float wr = w2[(i)*Cc + c];
            float wk = w2[(32 + i) * Cc + c];
            float wv = w2[(64 + i) * Cc + c];
#pragma unroll
            for (int r = 0; r < 4; r++) {
                mr[r] += sh[r][i] * wr;
                mk[r] += sh[r][32 + i] * wk;
                mv[r] += sh[r][64 + i] * wv;
            }
        }
        float tr = tmr[c], tk = tmk[c], tv = tmv[c];
#pragma unroll
        for (int r = 0; r < 4; r++) {
            int idx = (r0 + r) * Cc + c;
            float xv = x[idx];
            float dx = s_dx[idx];
            s_xq[idx] = xv + dx * (tr + mr[r]);
            s_xk[idx] = xv + dx * (tk + mk[r]);
            s_xv[idx] = xv + dx * (tv + mv[r]);
        }
    }
}

// ---------------- fp32 SGEMM core: 128x128x8 tiles, 256 thr, 8x8/thread ----
__device__ __forceinline__ void gemm_core(const float* __restrict__ A,
                                          const float* __restrict__ Bm,
                                          float* __restrict__ Co) {
    __shared__ float As[8][128];
    __shared__ float Bs[8][128];
    int tid = threadIdx.x;
    int m0 = blockIdx.y * 128, n0 = blockIdx.x * 128;
    int tx = tid & 15, ty = tid >> 4;
    int aRow = tid >> 1, aCol = (tid & 1) * 4;
    int bRow = tid >> 5, bCol = (tid & 31) * 4;
    float acc[64];
#pragma unroll
    for (int i = 0; i < 64; i++) acc[i] = 0.f;

    float4 av = *(const float4*)(A + (m0 + aRow) * Cc + aCol);
    float4 bv = *(const float4*)(Bm + bRow * Cc + n0 + bCol);

    for (int k0 = 0; k0 < Cc; k0 += 8) {
        As[aCol + 0][aRow] = av.x;
        As[aCol + 1][aRow] = av.y;
        As[aCol + 2][aRow] = av.z;
        As[aCol + 3][aRow] = av.w;
        *(float4*)&Bs[bRow][bCol] = bv;
        __syncthreads();
        if (k0 + 8 < Cc) {
            av = *(const float4*)(A + (m0 + aRow) * Cc + (k0 + 8) + aCol);
            bv = *(const float4*)(Bm + (k0 + 8 + bRow) * Cc + n0 + bCol);
        }
#pragma unroll
        for (int kk = 0; kk < 8; kk++) {
            float4 a0 = *(const float4*)&As[kk][ty * 8];
            float4 a1 = *(const float4*)&As[kk][ty * 8 + 4];
            float4 b0 = *(const float4*)&Bs[kk][tx * 8];
            float4 b1 = *(const float4*)&Bs[kk][tx * 8 + 4];
            float ar[8] = {a0.x, a0.y, a0.z, a0.w, a1.x, a1.y, a1.z, a1.w};
            float br[8] = {b0.x, b0.y, b0.z, b0.w, b1.x, b1.y, b1.z, b1.w};
#pragma unroll
            for (int i = 0; i < 8; i++)
#pragma unroll
                for (int j = 0; j < 8; j++) acc[i * 8 + j] += ar[i] * br[j];
        }
        __syncthreads();
    }
#pragma unroll
    for (int i = 0; i < 8; i++) {
        float* cp = Co + (m0 + ty * 8 + i) * Cc + n0 + tx * 8;
        float4 o0 = make_float4(acc[i * 8 + 0], acc[i * 8 + 1], acc[i * 8 + 2], acc[i * 8 + 3]);
        float4 o1 = make_float4(acc[i * 8 + 4], acc[i * 8 + 5], acc[i * 8 + 6], acc[i * 8 + 7]);
        *(float4*)cp = o0;
        *(float4*)(cp + 4) = o1;
    }
}

__global__ __launch_bounds__(256) void k_gemm_qkv(const float* __restrict__ Wq,
                                                  const float* __restrict__ Wk,
                                                  const float* __restrict__ Wv) {
    const float* A = (blockIdx.z == 0) ? s_xq : (blockIdx.z == 1) ? s_xk : s_xv;
    const float* W = (blockIdx.z == 0) ? Wq : (blockIdx.z == 1) ? Wk : Wv;
    float* Co = (blockIdx.z == 0) ? s_rq : (blockIdx.z == 1) ? s_rk : s_rv;
    gemm_core(A, W, Co);
}

__global__ __launch_bounds__(256) void k_gemm_out(const float* __restrict__ Wo,
                                                  float* __restrict__ out) {
    gemm_core(s_oln, Wo, out);
}

// ---------------- K5: LayerNorm (+RoPE for q,k), write (B,H,T,D) ----------
__global__ __launch_bounds__(256) void k_lnrope(const float* __restrict__ gr, const float* __restrict__ br,
                                                const float* __restrict__ gk, const float* __restrict__ bk,
                                                const float* __restrict__ gv, const float* __restrict__ bv,
                                                const float* __restrict__ cosp, const float* __restrict__ sinp) {
    int mode = blockIdx.y;
    const float* raw = (mode == 0) ? s_rq : (mode == 1) ? s_rk : s_rv;
    float* outp = (mode == 0) ? s_q : (mode == 1) ? s_k : s_v;
    const float* gp = (mode == 0) ? gr : (mode == 1) ? gk : gv;
    const float* bp = (mode == 0) ? br : (mode == 1) ? bk : bv;
    int bt = blockIdx.x;
    int t = bt & (Tt - 1);
    int b = bt >> 10;
    __shared__ float srow[Cc];
    __shared__ float red[16];
    float ls = 0.f, lq = 0.f;
    for (int c = threadIdx.x; c < Cc; c += 256) {
        float v = raw[bt * Cc + c];
        srow[c] = v;
        ls += v;
        lq += v * v;
    }
#pragma unroll
    for (int o = 16; o; o >>= 1) {
        ls += __shfl_xor_sync(0xffffffffu, ls, o);
        lq += __shfl_xor_sync(0xffffffffu, lq, o);
    }
    if ((threadIdx.x & 31) == 0) {
        red[threadIdx.x >> 5] = ls;
        red[8 + (threadIdx.x >> 5)] = lq;
    }
    __syncthreads();
    float sum = 0.f, sq = 0.f;
#pragma unroll
    for (int i = 0; i < 8; i++) {
        sum += red[i];
        sq += red[8 + i];
    }
    float mu = sum * (1.f / Cc);
    float var = sq * (1.f / Cc) - mu * mu;
    float rstd = rsqrtf(var + 1e-5f);
    for (int c = threadIdx.x; c < Cc; c += 256)
        srow[c] = (srow[c] - mu) * rstd * gp[c] + bp[c];
    __syncthreads();
    for (int c = threadIdx.x; c < Cc; c += 256) {
        int hh = c >> 6, d = c & 63;
        float y;
        if (mode < 2) {
            if (d < 32)
                y = srow[c] * cosp[t * 32 + d] - srow[c + 32] * sinp[t * 32 + d];
            else
                y = srow[c - 32] * sinp[t * 32 + d - 32] + srow[c] * cosp[t * 32 + d - 32];
        } else {
            y = srow[c];
        }
        outp[((b * Hh + hh) * Tt + t) * Dd + d] = y;
    }
}

// ---------------- K6: causal flash attention (BQ=BS=64, D=64) -------------
__global__ __launch_bounds__(256) void k_flash() {
    extern __shared__ float sm[];
    float* Qs = sm;                // 64 rows x 68
    float* Ks = sm + 64 * 68;
    float* Vs = sm + 2 * 64 * 68;
    float* Ps = sm + 3 * 64 * 68;
    int q0 = blockIdx.x * 64;
    int bh = blockIdx.y;
    int b = bh >> 5, h = bh & 31;
    const float* qp = s_q + (size_t)bh * Tt * Dd;
    const float* kp = s_k + (size_t)bh * Tt * Dd;
    const float* vp = s_v + (size_t)bh * Tt * Dd;
    int tid = threadIdx.x;
    int r = tid >> 2, q4 = tid & 3;

#pragma unroll
    for (int it = 0; it < 16; it++) {
        int lin = tid + it * 256;
        int row = lin >> 6, col = lin & 63;
        Qs[row * 68 + col] = qp[(q0 + row) * 64 + col];
    }
    float oa[16];
#pragma unroll
    for (int i = 0; i < 16; i++) oa[i] = 0.f;
    float m = NEG_INF, l = 0.f;
    int qi = q0 + r;

    for (int s0 = 0; s0 <= q0; s0 += 64) {
        __syncthreads();
#pragma unroll
        for (int it = 0; it < 16; it++) {
            int lin = tid + it * 256;
            int row = lin >> 6, col = lin & 63;
            Ks[row * 68 + col] = kp[(s0 + row) * 64 + col];
            Vs[row * 68 + col] = vp[(s0 + row) * 64 + col];
        }
        __syncthreads();

        float sc[16];
#pragma unroll
        for (int jj = 0; jj < 16; jj++) sc[jj] = 0.f;
        const float4* qrow = (const float4*)(Qs + r * 68);
#pragma unroll 4
        for (int d4 = 0; d4 < 16; d4++) {
            float4 qv = qrow[d4];
#pragma unroll
            for (int jj = 0; jj < 16; jj++) {
                float4 kv = *(const float4*)(Ks + (q4 * 16 + jj) * 68 + d4 * 4);
                sc[jj] += qv.x * kv.x + qv.y * kv.y + qv.z * kv.z + qv.w * kv.w;
            }
        }
        float mt = NEG_INF;
#pragma unroll
        for (int jj = 0; jj < 16; jj++) {
            int j = s0 + q4 * 16 + jj;
            sc[jj] = (j <= qi) ? sc[jj] * 0.125f : NEG_INF;
            mt = fmaxf(mt, sc[jj]);
        }
        mt = fmaxf(mt, __shfl_xor_sync(0xffffffffu, mt, 1));
        mt = fmaxf(mt, __shfl_xor_sync(0xffffffffu, mt, 2));
        float mn = fmaxf(m, mt);
        float corr = expf(m - mn);
        float ps = 0.f;
#pragma unroll
        for (int jj = 0; jj < 16; jj++) {
            float p = expf(sc[jj] - mn);
            Ps[r * 68 + q4 * 16 + jj] = p;
            ps += p;
        }
        ps += __shfl_xor_sync(0xffffffffu, ps, 1);
        ps += __shfl_xor_sync(0xffffffffu, ps, 2);
        l = l * corr + ps;
        m = mn;
#pragma unroll
        for (int i = 0; i < 16; i++) oa[i] *= corr;
        __syncthreads();
#pragma unroll 8
        for (int j = 0; j < 64; j++) {
            float pv = Ps[r * 68 + j];
            const float4* vr = (const float4*)(Vs + j * 68) + q4 * 4;
            float4 v0 = vr[0], v1 = vr[1], v2 = vr[2], v3 = vr[3];
            oa[0] += pv * v0.x;  oa[1] += pv * v0.y;  oa[2] += pv * v0.z;  oa[3] += pv * v0.w;
            oa[4] += pv * v1.x;  oa[5] += pv * v1.y;  oa[6] += pv * v1.z;  oa[7] += pv * v1.w;
            oa[8] += pv * v2.x;  oa[9] += pv * v2.y;  oa[10] += pv * v2.z; oa[11] += pv * v2.w;
            oa[12] += pv * v3.x; oa[13] += pv * v3.y; oa[14] += pv * v3.z; oa[15] += pv * v3.w;
        }
    }
    float inv = 1.f / l;
    float* op = s_o + ((size_t)(b * Tt + qi)) * Cc + h * 64 + q4 * 16;
#pragma unroll
    for (int i = 0; i < 16; i++) op[i] = oa[i] * inv;
}

// ---------------- K7: LayerNorm on o ----------------
__global__ __launch_bounds__(256) void k_lnout(const float* __restrict__ gx,
                                               const float* __restrict__ bx) {
    int bt = blockIdx.x;
    __shared__ float srow[Cc];
    __shared__ float red[16];
    float ls = 0.f, lq = 0.f;
    for (int c = threadIdx.x; c < Cc; c += 256) {
        float v = s_o[bt * Cc + c];
        srow[c] = v;
        ls += v;
        lq += v * v;
    }
#pragma unroll
    for (int o = 16; o; o >>= 1) {
        ls += __shfl_xor_sync(0xffffffffu, ls, o);
        lq += __shfl_xor_sync(0xffffffffu, lq, o);
    }
    if ((threadIdx.x & 31) == 0) {
        red[threadIdx.x >> 5] = ls;
        red[8 + (threadIdx.x >> 5)] = lq;
    }
    __syncthreads();
    float sum = 0.f, sq = 0.f;
#pragma unroll
    for (int i = 0; i < 8; i++) {
        sum += red[i];
        sq += red[8 + i];
    }
    float mu = sum * (1.f / Cc);
    float var = sq * (1.f / Cc) - mu * mu;
    float rstd = rsqrtf(var + 1e-5f);
    for (int c = threadIdx.x; c < Cc; c += 256)
        s_oln[bt * Cc + c] = (srow[c] - mu) * rstd * gx[c] + bx[c];
}

// ---------------- launch ----------------
extern "C" void kernel_launch(void* const* d_in, const int* in_sizes, int n_in,
                              void* d_out, int out_size) {
    const float* x = (const float*)d_in[0];
    const float* shift = (const float*)d_in[1];
    const float* tmx = (const float*)d_in[2];
    const float* tmr = (const float*)d_in[3];
    const float* tmk = (const float*)d_in[4];
    const float* tmv = (const float*)d_in[5];
    const float* w1 = (const float*)d_in[6];
    const float* w2 = (const float*)d_in[7];
    const float* Wq = (const float*)d_in[8];
    const float* Wk = (const float*)d_in[9];
    const float* Wv = (const float*)d_in[10];
    const float* Wo = (const float*)d_in[11];
    const float* gr = (const float*)d_in[12];
    const float* br = (const float*)d_in[13];
    const float* gk = (const float*)d_in[14];
    const float* bk = (const float*)d_in[15];
    const float* gv = (const float*)d_in[16];
    const float* bv = (const float*)d_in[17];
    const float* gx = (const float*)d_in[18];
    const float* bx = (const float*)d_in[19];
    const float* cosp = (const float*)d_in[20];
    const float* sinp = (const float*)d_in[21];
    float* out = (float*)d_out;

    k_shift<<<BTC / 256, 256>>>(x, shift, tmx);
    k_lora1<<<BT / 4, 96>>>(w1);
    k_mix<<<BT / 4, 256>>>(x, tmr, tmk, tmv, w2);
    k_gemm_qkv<<<dim3(16, 16, 3), 256>>>(Wq, Wk, Wv);
    k_lnrope<<<dim3(BT, 3), 256>>>(gr, br, gk, bk, gv, bv, cosp, sinp);
    cudaFuncSetAttribute(k_flash, cudaFuncAttributeMaxDynamicSharedMemorySize, 4 * 64 * 68 * 4);
    k_flash<<<dim3(16, 64), 256, 4 * 64 * 68 * 4>>>();
    k_lnout<<<BT, 256>>>(gx, bx);
    k_gemm_out<<<dim3(16, 16), 256>>>(Wo, out);
}

// round 2
// speedup vs baseline: 1.3981x; 1.3981x over previous
#include <cuda_runtime.h>
#include <math.h>
#include <stdint.h>

#define Bb 2
#define Tt 1024
#define Cc 2048
#define Hh 32
#define Dd 64
#define BT (Bb*Tt)
#define BTC (BT*Cc)
#define NEG_INF (-1e30f)

// ---------------- scratch (device globals; no allocation) ----------------
__device__ float s_dx[BTC];
__device__ float s_xxx[BTC];
__device__ float s_h[BT*96];
__device__ float s_xq[BTC];
__device__ float s_xk[BTC];
__device__ float s_xv[BTC];
__device__ float s_rq[BTC];
__device__ float s_rk[BTC];
__device__ float s_rv[BTC];
__device__ float s_q[BTC];   // (B,H,T,D)
__device__ float s_k[BTC];   // (B,H,T,D)
__device__ float s_v[BTC];   // (B,H,T,D)
__device__ float s_o[BTC];   // (B,T,C)
__device__ float s_oln[BTC];

// ---------------- K1: token shift + xxx ----------------
__global__ __launch_bounds__(256) void k_shift(const float* __restrict__ x,
                                               const float* __restrict__ shift,
                                               const float* __restrict__ tmx) {
    int i = blockIdx.x * 256 + threadIdx.x;
    int c = i & (Cc - 1);
    int bt = i >> 11;
    int t = bt & (Tt - 1);
    int b = bt >> 10;
    float xv = x[i];
    float xp = (t == 0) ? shift[b * Cc + c] : x[i - Cc];
    float dx = xp - xv;
    s_dx[i] = dx;
    s_xxx[i] = xv + dx * tmx[c];
}

// ---------------- K2: h = tanh(xxx @ w1), w1 is (C,96) ----------------
__global__ __launch_bounds__(96) void k_lora1(const float* __restrict__ w1) {
    __shared__ float sx[4][Cc];
    int r0 = blockIdx.x * 4;
    for (int i = threadIdx.x; i < 4 * Cc; i += 96) {
        sx[i >> 11][i & (Cc - 1)] = s_xxx[r0 * Cc + i];
    }
    __syncthreads();
    int j = threadIdx.x;  // 0..95
    float a0 = 0.f, a1 = 0.f, a2 = 0.f, a3 = 0.f;
    for (int c = 0; c < Cc; c++) {
        float w = w1[c * 96 + j];
        a0 += sx[0][c] * w;
        a1 += sx[1][c] * w;
        a2 += sx[2][c] * w;
        a3 += sx[3][c] * w;
    }
    s_h[(r0 + 0) * 96 + j] = tanhf(a0);
    s_h[(r0 + 1) * 96 + j] = tanhf(a1);
    s_h[(r0 + 2) * 96 + j] = tanhf(a2);
    s_h[(r0 + 3) * 96 + j] = tanhf(a3);
}

// ---------------- K3: m = h @ w2 (per l), then xq/xk/xv mix ----------------
__global__ __launch_bounds__(256) void k_mix(const float* __restrict__ x,
                                             const float* __restrict__ tmr,
                                             const float* __restrict__ tmk,
                                             const float* __restrict__ tmv,
                                             const float* __restrict__ w2) {
    __shared__ float sh[4][96];
    int r0 = blockIdx.x * 4;
    for (int i = threadIdx.x; i < 4 * 96; i += 256) {
        sh[i / 96][i % 96] = s_h[r0 * 96 + i];
    }
    __syncthreads();
    for (int c = threadIdx.x; c < Cc; c += 256) {
        float mr[4] = {0.f, 0.f, 0.f, 0.f};
        float mk[4] = {0.f, 0.f, 0.f, 0.f};
        float mv[4] = {0.f, 0.f, 0.f, 0.f};
#pragma unroll 8
        for (int i = 0; i < 32; i++) {
            float wr = w2[(i)*Cc + c];
            float wk = w2[(32 + i) * Cc + c];
            float wv = w2[(64 + i) * Cc + c];
#pragma unroll
            for (int r = 0; r < 4; r++) {
                mr[r] += sh[r][i] * wr;
                mk[r] += sh[r][32 + i] * wk;
                mv[r] += sh[r][64 + i] * wv;
            }
        }
        float tr = tmr[c], tk = tmk[c], tv = tmv[c];
#pragma unroll
        for (int r = 0; r < 4; r++) {
            int idx = (r0 + r) * Cc + c;
            float xv = x[idx];
            float dx = s_dx[idx];
            s_xq[idx] = xv + dx * (tr + mr[r]);
            s_xk[idx] = xv + dx * (tk + mk[r]);
            s_xv[idx] = xv + dx * (tv + mv[r]);
        }
    }
}

// ---------------- TF32 tensor-core GEMM: 128x128 tile, BK=32 ----------------
__device__ __forceinline__ uint32_t f2tf(float f) {
    uint32_t u;
    asm("cvt.rna.tf32.f32 %0, %1;" : "=r"(u) : "f"(f));
    return u;
}

#define AS_STRIDE 36
#define BS_STRIDE 136

__device__ __forceinline__ void gemm_tf32(const float* __restrict__ A,
                                          const float* __restrict__ W,
                                          float* __restrict__ Co) {
    __shared__ uint32_t As[128 * AS_STRIDE];   // [m][k] padded
    __shared__ uint32_t Bs[32 * BS_STRIDE];    // [k][n] padded
    int tid = threadIdx.x;
    int m0 = blockIdx.y * 128, n0 = blockIdx.x * 128;
    int warp = tid >> 5, lane = tid & 31;
    int wm = (warp & 3) * 32;      // 4 warps along M
    int wn = (warp >> 2) * 64;     // 2 warps along N
    int gid = lane >> 2, tig = lane & 3;

    int ar = tid >> 3, ac = (tid & 7) * 4;    // A: rows ar+32i, cols ac
    int br = tid >> 5, bc = (tid & 31) * 4;   // B: rows br+8i, cols bc
    const float* Ap = A + (m0 + ar) * Cc + ac;
    const float* Wp = W + br * Cc + n0 + bc;

    float4 pa[4], pb[4];
#pragma unroll
    for (int i = 0; i < 4; i++) {
        pa[i] = *(const float4*)(Ap + i * 32 * Cc);
        pb[i] = *(const float4*)(Wp + i * 8 * Cc);
    }

    float acc[2][8][4];
#pragma unroll
    for (int mt = 0; mt < 2; mt++)
#pragma unroll
        for (int nt = 0; nt < 8; nt++)
#pragma unroll
            for (int i = 0; i < 4; i++) acc[mt][nt][i] = 0.f;

    for (int k0 = 0; k0 < Cc; k0 += 32) {
#pragma unroll
        for (int i = 0; i < 4; i++) {
            uint32_t* sa = &As[(ar + 32 * i) * AS_STRIDE + ac];
            sa[0] = f2tf(pa[i].x); sa[1] = f2tf(pa[i].y);
            sa[2] = f2tf(pa[i].z); sa[3] = f2tf(pa[i].w);
            uint32_t* sb = &Bs[(br + 8 * i) * BS_STRIDE + bc];
            sb[0] = f2tf(pb[i].x); sb[1] = f2tf(pb[i].y);
            sb[2] = f2tf(pb[i].z); sb[3] = f2tf(pb[i].w);
        }
        __syncthreads();
        if (k0 + 32 < Cc) {
            Ap += 32;
            Wp += 32 * Cc;
#pragma unroll
            for (int i = 0; i < 4; i++) {
                pa[i] = *(const float4*)(Ap + i * 32 * Cc);
                pb[i] = *(const float4*)(Wp + i * 8 * Cc);
            }
        }
#pragma unroll
        for (int kk = 0; kk < 4; kk++) {
            int kb = kk * 8;
            uint32_t af[2][4], bf[8][2];
#pragma unroll
            for (int mt = 0; mt < 2; mt++) {
                const uint32_t* ap = &As[(wm + mt * 16 + gid) * AS_STRIDE + kb + tig];
                af[mt][0] = ap[0];
                af[mt][1] = ap[8 * AS_STRIDE];
                af[mt][2] = ap[4];
                af[mt][3] = ap[8 * AS_STRIDE + 4];
            }
#pragma unroll
            for (int nt = 0; nt < 8; nt++) {
                const uint32_t* bp = &Bs[(kb + tig) * BS_STRIDE + wn + nt * 8 + gid];
                bf[nt][0] = bp[0];
                bf[nt][1] = bp[4 * BS_STRIDE];
            }
#pragma unroll
            for (int mt = 0; mt < 2; mt++)
#pragma unroll
                for (int nt = 0; nt < 8; nt++) {
                    asm volatile(
                        "mma.sync.aligned.m16n8k8.row.col.f32.tf32.tf32.f32 "
                        "{%0,%1,%2,%3}, {%4,%5,%6,%7}, {%8,%9}, {%0,%1,%2,%3};"
                        : "+f"(acc[mt][nt][0]), "+f"(acc[mt][nt][1]),
                          "+f"(acc[mt][nt][2]), "+f"(acc[mt][nt][3])
                        : "r"(af[mt][0]), "r"(af[mt][1]), "r"(af[mt][2]), "r"(af[mt][3]),
                          "r"(bf[nt][0]), "r"(bf[nt][1]));
                }
        }
        __syncthreads();
    }
#pragma unroll
    for (int mt = 0; mt < 2; mt++)
#pragma unroll
        for (int nt = 0; nt < 8; nt++) {
            int row = m0 + wm + mt * 16 + gid;
            int col = n0 + wn + nt * 8 + tig * 2;
            *(float2*)&Co[row * Cc + col] = make_float2(acc[mt][nt][0], acc[mt][nt][1]);
            *(float2*)&Co[(row + 8) * Cc + col] = make_float2(acc[mt][nt][2], acc[mt][nt][3]);
        }
}

__global__ __launch_bounds__(256) void k_gemm_qkv(const float* __restrict__ Wq,
                                                  const float* __restrict__ Wk,
                                                  const float* __restrict__ Wv) {
    const float* A = (blockIdx.z == 0) ? s_xq : (blockIdx.z == 1) ? s_xk : s_xv;
    const float* W = (blockIdx.z == 0) ? Wq : (blockIdx.z == 1) ? Wk : Wv;
    float* Co = (blockIdx.z == 0) ? s_rq : (blockIdx.z == 1) ? s_rk : s_rv;
    gemm_tf32(A, W, Co);
}

__global__ __launch_bounds__(256) void k_gemm_out(const float* __restrict__ Wo,
                                                  float* __restrict__ out) {
    gemm_tf32(s_oln, Wo, out);
}

// ---------------- K5: LayerNorm (+RoPE for q,k), write (B,H,T,D) ----------
__global__ __launch_bounds__(256) void k_lnrope(const float* __restrict__ gr, const float* __restrict__ br,
                                                const float* __restrict__ gk, const float* __restrict__ bk,
                                                const float* __restrict__ gv, const float* __restrict__ bv,
                                                const float* __restrict__ cosp, const float* __restrict__ sinp) {
    int mode = blockIdx.y;
    const float* raw = (mode == 0) ? s_rq : (mode == 1) ? s_rk : s_rv;
    float* outp = (mode == 0) ? s_q : (mode == 1) ? s_k : s_v;
    const float* gp = (mode == 0) ? gr : (mode == 1) ? gk : gv;
    const float* bp = (mode == 0) ? br : (mode == 1) ? bk : bv;
    int bt = blockIdx.x;
    int t = bt & (Tt - 1);
    int b = bt >> 10;
    __shared__ float srow[Cc];
    __shared__ float red[16];
    float ls = 0.f, lq = 0.f;
    for (int c = threadIdx.x; c < Cc; c += 256) {
        float v = raw[bt * Cc + c];
        srow[c] = v;
        ls += v;
        lq += v * v;
    }
#pragma unroll
    for (int o = 16; o; o >>= 1) {
        ls += __shfl_xor_sync(0xffffffffu, ls, o);
        lq += __shfl_xor_sync(0xffffffffu, lq, o);
    }
    if ((threadIdx.x & 31) == 0) {
        red[threadIdx.x >> 5] = ls;
        red[8 + (threadIdx.x >> 5)] = lq;
    }
    __syncthreads();
    float sum = 0.f, sq = 0.f;
#pragma unroll
    for (int i = 0; i < 8; i++) {
        sum += red[i];
        sq += red[8 + i];
    }
    float mu = sum * (1.f / Cc);
    float var = sq * (1.f / Cc) - mu * mu;
    float rstd = rsqrtf(var + 1e-5f);
    for (int c = threadIdx.x; c < Cc; c += 256)
        srow[c] = (srow[c] - mu) * rstd * gp[c] + bp[c];
    __syncthreads();
    for (int c = threadIdx.x; c < Cc; c += 256) {
        int hh = c >> 6, d = c & 63;
        float y;
        if (mode < 2) {
            if (d < 32)
                y = srow[c] * cosp[t * 32 + d] - srow[c + 32] * sinp[t * 32 + d];
            else
                y = srow[c - 32] * sinp[t * 32 + d - 32] + srow[c] * cosp[t * 32 + d - 32];
        } else {
            y = srow[c];
        }
        outp[((b * Hh + hh) * Tt + t) * Dd + d] = y;
    }
}

// ---------------- K6: causal flash attention (BQ=BS=64, D=64) -------------
__global__ __launch_bounds__(256) void k_flash() {
    extern __shared__ float sm[];
    float* Qs = sm;                // 64 rows x 68
    float* Ks = sm + 64 * 68;
    float* Vs = sm + 2 * 64 * 68;
    float* Ps = sm + 3 * 64 * 68;
    int q0 = blockIdx.x * 64;
    int bh = blockIdx.y;
    int b = bh >> 5, h = bh & 31;
    const float* qp = s_q + (size_t)bh * Tt * Dd;
    const float* kp = s_k + (size_t)bh * Tt * Dd;
    const float* vp = s_v + (size_t)bh * Tt * Dd;
    int tid = threadIdx.x;
    int r = tid >> 2, q4 = tid & 3;

#pragma unroll
    for (int it = 0; it < 16; it++) {
        int lin = tid + it * 256;
        int row = lin >> 6, col = lin & 63;
        Qs[row * 68 + col] = qp[(q0 + row) * 64 + col];
    }
    float oa[16];
#pragma unroll
    for (int i = 0; i < 16; i++) oa[i] = 0.f;
    float m = NEG_INF, l = 0.f;
    int qi = q0 + r;

    for (int s0 = 0; s0 <= q0; s0 += 64) {
        __syncthreads();
#pragma unroll
        for (int it = 0; it < 16; it++) {
            int lin = tid + it * 256;
            int row = lin >> 6, col = lin & 63;
            Ks[row * 68 + col] = kp[(s0 + row) * 64 + col];
            Vs[row * 68 + col] = vp[(s0 + row) * 64 + col];
        }
        __syncthreads();

        float sc[16];
#pragma unroll
        for (int jj = 0; jj < 16; jj++) sc[jj] = 0.f;
        const float4* qrow = (const float4*)(Qs + r * 68);
#pragma unroll 4
        for (int d4 = 0; d4 < 16; d4++) {
            float4 qv = qrow[d4];
#pragma unroll
            for (int jj = 0; jj < 16; jj++) {
                float4 kv = *(const float4*)(Ks + (q4 * 16 + jj) * 68 + d4 * 4);
                sc[jj] += qv.x * kv.x + qv.y * kv.y + qv.z * kv.z + qv.w * kv.w;
            }
        }
        float mt = NEG_INF;
#pragma unroll
        for (int jj = 0; jj < 16; jj++) {
            int j = s0 + q4 * 16 + jj;
            sc[jj] = (j <= qi) ? sc[jj] * 0.125f : NEG_INF;
            mt = fmaxf(mt, sc[jj]);
        }
        mt = fmaxf(mt, __shfl_xor_sync(0xffffffffu, mt, 1));
        mt = fmaxf(mt, __shfl_xor_sync(0xffffffffu, mt, 2));
        float mn = fmaxf(m, mt);
        float corr = expf(m - mn);
        float ps = 0.f;
#pragma unroll
        for (int jj = 0; jj < 16; jj++) {
            float p = expf(sc[jj] - mn);
            Ps[r * 68 + q4 * 16 + jj] = p;
            ps += p;
        }
        ps += __shfl_xor_sync(0xffffffffu, ps, 1);
        ps += __shfl_xor_sync(0xffffffffu, ps, 2);
        l = l * corr + ps;
        m = mn;
#pragma unroll
        for (int i = 0; i < 16; i++) oa[i] *= corr;
        __syncthreads();
#pragma unroll 8
        for (int j = 0; j < 64; j++) {
            float pv = Ps[r * 68 + j];
            const float4* vr = (const float4*)(Vs + j * 68) + q4 * 4;
            float4 v0 = vr[0], v1 = vr[1], v2 = vr[2], v3 = vr[3];
            oa[0] += pv * v0.x;  oa[1] += pv * v0.y;  oa[2] += pv * v0.z;  oa[3] += pv * v0.w;
            oa[4] += pv * v1.x;  oa[5] += pv * v1.y;  oa[6] += pv * v1.z;  oa[7] += pv * v1.w;
            oa[8] += pv * v2.x;  oa[9] += pv * v2.y;  oa[10] += pv * v2.z; oa[11] += pv * v2.w;
            oa[12] += pv * v3.x; oa[13] += pv * v3.y; oa[14] += pv * v3.z; oa[15] += pv * v3.w;
        }
    }
    float inv = 1.f / l;
    float* op = s_o + ((size_t)(b * Tt + qi)) * Cc + h * 64 + q4 * 16;
#pragma unroll
    for (int i = 0; i < 16; i++) op[i] = oa[i] * inv;
}

// ---------------- K7: LayerNorm on o ----------------
__global__ __launch_bounds__(256) void k_lnout(const float* __restrict__ gx,
                                               const float* __restrict__ bx) {
    int bt = blockIdx.x;
    __shared__ float srow[Cc];
    __shared__ float red[16];
    float ls = 0.f, lq = 0.f;
    for (int c = threadIdx.x; c < Cc; c += 256) {
        float v = s_o[bt * Cc + c];
        srow[c] = v;
        ls += v;
        lq += v * v;
    }
#pragma unroll
    for (int o = 16; o; o >>= 1) {
        ls += __shfl_xor_sync(0xffffffffu, ls, o);
        lq += __shfl_xor_sync(0xffffffffu, lq, o);
    }
    if ((threadIdx.x & 31) == 0) {
        red[threadIdx.x >> 5] = ls;
        red[8 + (threadIdx.x >> 5)] = lq;
    }
    __syncthreads();
    float sum = 0.f, sq = 0.f;
#pragma unroll
    for (int i = 0; i < 8; i++) {
        sum += red[i];
        sq += red[8 + i];
    }
    float mu = sum * (1.f / Cc);
    float var = sq * (1.f / Cc) - mu * mu;
    float rstd = rsqrtf(var + 1e-5f);
    for (int c = threadIdx.x; c < Cc; c += 256)
        s_oln[bt * Cc + c] = (srow[c] - mu) * rstd * gx[c] + bx[c];
}

// ---------------- launch ----------------
extern "C" void kernel_launch(void* const* d_in, const int* in_sizes, int n_in,
                              void* d_out, int out_size) {
    const float* x = (const float*)d_in[0];
    const float* shift = (const float*)d_in[1];
    const float* tmx = (const float*)d_in[2];
    const float* tmr = (const float*)d_in[3];
    const float* tmk = (const float*)d_in[4];
    const float* tmv = (const float*)d_in[5];
    const float* w1 = (const float*)d_in[6];
    const float* w2 = (const float*)d_in[7];
    const float* Wq = (const float*)d_in[8];
    const float* Wk = (const float*)d_in[9];
    const float* Wv = (const float*)d_in[10];
    const float* Wo = (const float*)d_in[11];
    const float* gr = (const float*)d_in[12];
    const float* br = (const float*)d_in[13];
    const float* gk = (const float*)d_in[14];
    const float* bk = (const float*)d_in[15];
    const float* gv = (const float*)d_in[16];
    const float* bv = (const float*)d_in[17];
    const float* gx = (const float*)d_in[18];
    const float* bx = (const float*)d_in[19];
    const float* cosp = (const float*)d_in[20];
    const float* sinp = (const float*)d_in[21];
    float* out = (float*)d_out;

    k_shift<<<BTC / 256, 256>>>(x, shift, tmx);
    k_lora1<<<BT / 4, 96>>>(w1);
    k_mix<<<BT / 4, 256>>>(x, tmr, tmk, tmv, w2);
    k_gemm_qkv<<<dim3(16, 16, 3), 256>>>(Wq, Wk, Wv);
    k_lnrope<<<dim3(BT, 3), 256>>>(gr, br, gk, bk, gv, bv, cosp, sinp);
    cudaFuncSetAttribute(k_flash, cudaFuncAttributeMaxDynamicSharedMemorySize, 4 * 64 * 68 * 4);
    k_flash<<<dim3(16, 64), 256, 4 * 64 * 68 * 4>>>();
    k_lnout<<<BT, 256>>>(gx, bx);
    k_gemm_out<<<dim3(16, 16), 256>>>(Wo, out);
}

// round 5
// speedup vs baseline: 4.0725x; 2.9128x over previous
#include <cuda_runtime.h>
#include <math.h>
#include <stdint.h>

#define Bb 2
#define Tt 1024
#define Cc 2048
#define Hh 32
#define Dd 64
#define BT (Bb*Tt)
#define BTC (BT*Cc)
#define NEG_INF (-1e30f)

// ---------------- scratch (device globals; no allocation) ----------------
__device__ float s_dx[BTC];
__device__ float s_xxx[BTC];
__device__ float s_h[BT*96];
__device__ float s_xq[BTC];
__device__ float s_xk[BTC];
__device__ float s_xv[BTC];
__device__ float s_rq[BTC];
__device__ float s_rk[BTC];
__device__ float s_rv[BTC];
__device__ float s_q[BTC];   // (B,H,T,D)
__device__ float s_k[BTC];   // (B,H,T,D)
__device__ float s_v[BTC];   // (B,H,T,D)
__device__ float s_o[BTC];   // (B,T,C)
__device__ float s_oln[BTC];

__device__ __forceinline__ uint32_t f2tf(float f) {
    uint32_t u;
    asm("cvt.rna.tf32.f32 %0, %1;" : "=r"(u) : "f"(f));
    return u;
}

// ---------------- K1: token shift + xxx ----------------
__global__ __launch_bounds__(256) void k_shift(const float* __restrict__ x,
                                               const float* __restrict__ shift,
                                               const float* __restrict__ tmx) {
    int i = blockIdx.x * 256 + threadIdx.x;
    int c = i & (Cc - 1);
    int bt = i >> 11;
    int t = bt & (Tt - 1);
    int b = bt >> 10;
    float xv = x[i];
    float xp = (t == 0) ? shift[b * Cc + c] : x[i - Cc];
    float dx = xp - xv;
    s_dx[i] = dx;
    s_xxx[i] = xv + dx * tmx[c];
}

// ---------------- K2: h = tanh(xxx @ w1), w1 is (C,96) ----------------
__global__ __launch_bounds__(96) void k_lora1(const float* __restrict__ w1) {
    __shared__ float sx[4][Cc];
    int r0 = blockIdx.x * 4;
    for (int i = threadIdx.x; i < 4 * Cc; i += 96) {
        sx[i >> 11][i & (Cc - 1)] = s_xxx[r0 * Cc + i];
    }
    __syncthreads();
    int j = threadIdx.x;  // 0..95
    float a0 = 0.f, a1 = 0.f, a2 = 0.f, a3 = 0.f;
    for (int c = 0; c < Cc; c += 8) {
        float wb[8];
#pragma unroll
        for (int u = 0; u < 8; u++) wb[u] = w1[(c + u) * 96 + j];
#pragma unroll
        for (int u = 0; u < 8; u++) {
            float w = wb[u];
            a0 += sx[0][c + u] * w;
            a1 += sx[1][c + u] * w;
            a2 += sx[2][c + u] * w;
            a3 += sx[3][c + u] * w;
        }
    }
    s_h[(r0 + 0) * 96 + j] = tanhf(a0);
    s_h[(r0 + 1) * 96 + j] = tanhf(a1);
    s_h[(r0 + 2) * 96 + j] = tanhf(a2);
    s_h[(r0 + 3) * 96 + j] = tanhf(a3);
}

// ---------------- K3: m = h @ w2 (per l), then xq/xk/xv mix ----------------
__global__ __launch_bounds__(256) void k_mix(const float* __restrict__ x,
                                             const float* __restrict__ tmr,
                                             const float* __restrict__ tmk,
                                             const float* __restrict__ tmv,
                                             const float* __restrict__ w2) {
    __shared__ float sh[4][96];
    int r0 = blockIdx.x * 4;
    for (int i = threadIdx.x; i < 4 * 96; i += 256) {
        sh[i / 96][i % 96] = s_h[r0 * 96 + i];
    }
    __syncthreads();
    for (int c = threadIdx.x; c < Cc; c += 256) {
        float mr[4] = {0.f, 0.f, 0.f, 0.f};
        float mk[4] = {0.f, 0.f, 0.f, 0.f};
        float mv[4] = {0.f, 0.f, 0.f, 0.f};
#pragma unroll 8
        for (int i = 0; i < 32; i++) {
            float wr = w2[(i)*Cc + c];
            float wk = w2[(32 + i) * Cc + c];
            float wv = w2[(64 + i) * Cc + c];
#pragma unroll
            for (int r = 0; r < 4; r++) {
                mr[r] += sh[r][i] * wr;
                mk[r] += sh[r][32 + i] * wk;
                mv[r] += sh[r][64 + i] * wv;
            }
        }
        float tr = tmr[c], tk = tmk[c], tv = tmv[c];
#pragma unroll
        for (int r = 0; r < 4; r++) {
            int idx = (r0 + r) * Cc + c;
            float xv = x[idx];
            float dx = s_dx[idx];
            s_xq[idx] = xv + dx * (tr + mr[r]);
            s_xk[idx] = xv + dx * (tk + mk[r]);
            s_xv[idx] = xv + dx * (tv + mv[r]);
        }
    }
}

// ---------------- TF32 tensor-core GEMM: 128x128 tile, BK=32, 2-stage -----
#define AS_STRIDE 36
#define BS_STRIDE 136
#define ASZ (128 * AS_STRIDE)
#define BSZ (32 * BS_STRIDE)
#define GEMM_SMEM (2 * (ASZ + BSZ) * 4)

__device__ __forceinline__ void gemm_tf32(const float* __restrict__ A,
                                          const float* __restrict__ W,
                                          float* __restrict__ Co) {
    extern __shared__ uint32_t gsm[];
    uint32_t* AsB = gsm;            // [2][ASZ]
    uint32_t* BsB = gsm + 2 * ASZ;  // [2][BSZ]
    int tid = threadIdx.x;
    int m0 = blockIdx.y * 128, n0 = blockIdx.x * 128;
    int warp = tid >> 5, lane = tid & 31;
    int wm = (warp & 3) * 32;      // 4 warps along M
    int wn = (warp >> 2) * 64;     // 2 warps along N
    int gid = lane >> 2, tig = lane & 3;

    int ar = tid >> 3, ac = (tid & 7) * 4;    // A: rows ar+32i, cols ac
    int br = tid >> 5, bc = (tid & 31) * 4;   // B: rows br+8i, cols bc
    const float* Ap = A + (m0 + ar) * Cc + ac;
    const float* Wp = W + br * Cc + n0 + bc;

    float4 pa[4], pb[4];
#pragma unroll
    for (int i = 0; i < 4; i++) {
        pa[i] = *(const float4*)(Ap + i * 32 * Cc);
        pb[i] = *(const float4*)(Wp + i * 8 * Cc);
    }
    // store stage 0
#pragma unroll
    for (int i = 0; i < 4; i++) {
        uint4 va = make_uint4(f2tf(pa[i].x), f2tf(pa[i].y), f2tf(pa[i].z), f2tf(pa[i].w));
        *(uint4*)&AsB[(ar + 32 * i) * AS_STRIDE + ac] = va;
        uint4 vb = make_uint4(f2tf(pb[i].x), f2tf(pb[i].y), f2tf(pb[i].z), f2tf(pb[i].w));
        *(uint4*)&BsB[(br + 8 * i) * BS_STRIDE + bc] = vb;
    }

    float acc[2][8][4];
#pragma unroll
    for (int mt = 0; mt < 2; mt++)
#pragma unroll
        for (int nt = 0; nt < 8; nt++)
#pragma unroll
            for (int i = 0; i < 4; i++) acc[mt][nt][i] = 0.f;

    int p = 0;
    for (int k0 = 0; k0 < Cc; k0 += 32) {
        __syncthreads();
        bool next = (k0 + 32) < Cc;
        if (next) {
            Ap += 32;
            Wp += 32 * Cc;
#pragma unroll
            for (int i = 0; i < 4; i++) {
                pa[i] = *(const float4*)(Ap + i * 32 * Cc);
                pb[i] = *(const float4*)(Wp + i * 8 * Cc);
            }
        }
        const uint32_t* As = AsB + p * ASZ;
        const uint32_t* Bs = BsB + p * BSZ;
#pragma unroll
        for (int kk = 0; kk < 4; kk++) {
            int kb = kk * 8;
            uint32_t af[2][4], bf[8][2];
#pragma unroll
            for (int mt = 0; mt < 2; mt++) {
                const uint32_t* ap = &As[(wm + mt * 16 + gid) * AS_STRIDE + kb + tig];
                af[mt][0] = ap[0];
                af[mt][1] = ap[8 * AS_STRIDE];
                af[mt][2] = ap[4];
                af[mt][3] = ap[8 * AS_STRIDE + 4];
            }
#pragma unroll
            for (int nt = 0; nt < 8; nt++) {
                const uint32_t* bp = &Bs[(kb + tig) * BS_STRIDE + wn + nt * 8 + gid];
                bf[nt][0] = bp[0];
                bf[nt][1] = bp[4 * BS_STRIDE];
            }
#pragma unroll
            for (int mt = 0; mt < 2; mt++)
#pragma unroll
                for (int nt = 0; nt < 8; nt++) {
                    asm volatile(
                        "mma.sync.aligned.m16n8k8.row.col.f32.tf32.tf32.f32 "
                        "{%0,%1,%2,%3}, {%4,%5,%6,%7}, {%8,%9}, {%0,%1,%2,%3};"
                        : "+f"(acc[mt][nt][0]), "+f"(acc[mt][nt][1]),
                          "+f"(acc[mt][nt][2]), "+f"(acc[mt][nt][3])
                        : "r"(af[mt][0]), "r"(af[mt][1]), "r"(af[mt][2]), "r"(af[mt][3]),
                          "r"(bf[nt][0]), "r"(bf[nt][1]));
                }
        }
        if (next) {
            uint32_t* Asn = AsB + (p ^ 1) * ASZ;
            uint32_t* Bsn = BsB + (p ^ 1) * BSZ;
#pragma unroll
            for (int i = 0; i < 4; i++) {
                uint4 va = make_uint4(f2tf(pa[i].x), f2tf(pa[i].y), f2tf(pa[i].z), f2tf(pa[i].w));
                *(uint4*)&Asn[(ar + 32 * i) * AS_STRIDE + ac] = va;
                uint4 vb = make_uint4(f2tf(pb[i].x), f2tf(pb[i].y), f2tf(pb[i].z), f2tf(pb[i].w));
                *(uint4*)&Bsn[(br + 8 * i) * BS_STRIDE + bc] = vb;
            }
        }
        p ^= 1;
    }
#pragma unroll
    for (int mt = 0; mt < 2; mt++)
#pragma unroll
        for (int nt = 0; nt < 8; nt++) {
            int row = m0 + wm + mt * 16 + gid;
            int col = n0 + wn + nt * 8 + tig * 2;
            *(float2*)&Co[row * Cc + col] = make_float2(acc[mt][nt][0], acc[mt][nt][1]);
            *(float2*)&Co[(row + 8) * Cc + col] = make_float2(acc[mt][nt][2], acc[mt][nt][3]);
        }
}

__global__ __launch_bounds__(256) void k_gemm_qkv(const float* __restrict__ Wq,
                                                  const float* __restrict__ Wk,
                                                  const float* __restrict__ Wv) {
    const float* A = (blockIdx.z == 0) ? s_xq : (blockIdx.z == 1) ? s_xk : s_xv;
    const float* W = (blockIdx.z == 0) ? Wq : (blockIdx.z == 1) ? Wk : Wv;
    float* Co = (blockIdx.z == 0) ? s_rq : (blockIdx.z == 1) ? s_rk : s_rv;
    gemm_tf32(A, W, Co);
}

__global__ __launch_bounds__(256) void k_gemm_out(const float* __restrict__ Wo,
                                                  float* __restrict__ out) {
    gemm_tf32(s_oln, Wo, out);
}

// ---------------- K5: LayerNorm (+RoPE for q,k), write (B,H,T,D) ----------
__global__ __launch_bounds__(256) void k_lnrope(const float* __restrict__ gr, const float* __restrict__ br,
                                                const float* __restrict__ gk, const float* __restrict__ bk,
                                                const float* __restrict__ gv, const float* __restrict__ bv,
                                                const float* __restrict__ cosp, const float* __restrict__ sinp) {
    int mode = blockIdx.y;
    const float* raw = (mode == 0) ? s_rq : (mode == 1) ? s_rk : s_rv;
    float* outp = (mode == 0) ? s_q : (mode == 1) ? s_k : s_v;
    const float* gp = (mode == 0) ? gr : (mode == 1) ? gk : gv;
    const float* bp = (mode == 0) ? br : (mode == 1) ? bk : bv;
    int bt = blockIdx.x;
    int t = bt & (Tt - 1);
    int b = bt >> 10;
    __shared__ float srow[Cc];
    __shared__ float red[16];
    float ls = 0.f, lq = 0.f;
    for (int c = threadIdx.x; c < Cc; c += 256) {
        float v = raw[bt * Cc + c];
        srow[c] = v;
        ls += v;
        lq += v * v;
    }
#pragma unroll
    for (int o = 16; o; o >>= 1) {
        ls += __shfl_xor_sync(0xffffffffu, ls, o);
        lq += __shfl_xor_sync(0xffffffffu, lq, o);
    }
    if ((threadIdx.x & 31) == 0) {
        red[threadIdx.x >> 5] = ls;
        red[8 + (threadIdx.x >> 5)] = lq;
    }
    __syncthreads();
    float sum = 0.f, sq = 0.f;
#pragma unroll
    for (int i = 0; i < 8; i++) {
        sum += red[i];
        sq += red[8 + i];
    }
    float mu = sum * (1.f / Cc);
    float var = sq * (1.f / Cc) - mu * mu;
    float rstd = rsqrtf(var + 1e-5f);
    for (int c = threadIdx.x; c < Cc; c += 256)
        srow[c] = (srow[c] - mu) * rstd * gp[c] + bp[c];
    __syncthreads();
    for (int c = threadIdx.x; c < Cc; c += 256) {
        int hh = c >> 6, d = c & 63;
        float y;
        if (mode < 2) {
            if (d < 32)
                y = srow[c] * cosp[t * 32 + d] - srow[c + 32] * sinp[t * 32 + d];
            else
                y = srow[c - 32] * sinp[t * 32 + d - 32] + srow[c] * cosp[t * 32 + d - 32];
        } else {
            y = srow[c];
        }
        outp[((b * Hh + hh) * Tt + t) * Dd + d] = y;
    }
}

// ---------------- K6: tensor-core causal flash attention ------------------
// BQ=BKV=64, D=64, 256 threads = 8 warps (warp grid 4(q) x 2(s|d)).
// S = Q K^T via 3x tf32 (hi/lo split); P V via single tf32.
#define SD 68    // stride for Qh/Ql/Kh/Kl/Pt (u32)
#define SDV 72   // stride for Vt
#define FL_TILE (64 * SD)
#define FL_SMEM ((5 * FL_TILE + 64 * SDV + 256) * 4)

__global__ __launch_bounds__(256) void k_flash() {
    extern __shared__ uint32_t fsm[];
    uint32_t* Qh = fsm;
    uint32_t* Ql = Qh + FL_TILE;
    uint32_t* Kh = Ql + FL_TILE;
    uint32_t* Kl = Kh + FL_TILE;
    uint32_t* Pt = Kl + FL_TILE;
    uint32_t* Vt = Pt + FL_TILE;       // 64*SDV
    float* red = (float*)(Vt + 64 * SDV);  // [0..127] max, [128..255] sum

    int tid = threadIdx.x;
    int warp = tid >> 5, lane = tid & 31;
    int gid = lane >> 2, tig = lane & 3;
    int qw = (warp & 3) * 16;   // warp q-row base
    int sh = warp >> 2;         // warp half (s for S, d for O)
    int sb = sh * 32;

    int q0 = blockIdx.x * 64;
    int bh = blockIdx.y;
    int b = bh >> 5, h = bh & 31;
    const float* qp = s_q + (size_t)bh * Tt * Dd;
    const float* kp = s_k + (size_t)bh * Tt * Dd;
    const float* vp = s_v + (size_t)bh * Tt * Dd;

    // load Q tile (scaled by 1/8), hi/lo split
#pragma unroll
    for (int it = 0; it < 4; it++) {
        int lin = tid + it * 256;        // over 1024 float4s
        int row = lin >> 4, c4 = (lin & 15) * 4;
        float4 v = *(const float4*)(qp + (q0 + row) * 64 + c4);
        v.x *= 0.125f; v.y *= 0.125f; v.z *= 0.125f; v.w *= 0.125f;
        uint4 hi = make_uint4(f2tf(v.x), f2tf(v.y), f2tf(v.z), f2tf(v.w));
        uint4 lo = make_uint4(f2tf(v.x - __uint_as_float(hi.x)),
                              f2tf(v.y - __uint_as_float(hi.y)),
                              f2tf(v.z - __uint_as_float(hi.z)),
                              f2tf(v.w - __uint_as_float(hi.w)));
        *(uint4*)&Qh[row * SD + c4] = hi;
        *(uint4*)&Ql[row * SD + c4] = lo;
    }

    float oacc[4][4];
#pragma unroll
    for (int nt = 0; nt < 4; nt++)
#pragma unroll
        for (int i = 0; i < 4; i++) oacc[nt][i] = 0.f;
    float m0 = NEG_INF, m1 = NEG_INF, l0 = 0.f, l1 = 0.f;
    int row0 = q0 + qw + gid;   // global q row for c0,c1
    int row1 = row0 + 8;

    for (int s0 = 0; s0 <= q0; s0 += 64) {
        __syncthreads();   // guard tile reuse
        // load K (hi/lo) and V (tf32)
#pragma unroll
        for (int it = 0; it < 4; it++) {
            int lin = tid + it * 256;
            int row = lin >> 4, c4 = (lin & 15) * 4;
            float4 kv = *(const float4*)(kp + (s0 + row) * 64 + c4);
            uint4 hi = make_uint4(f2tf(kv.x), f2tf(kv.y), f2tf(kv.z), f2tf(kv.w));
            uint4 lo = make_uint4(f2tf(kv.x - __uint_as_float(hi.x)),
                                  f2tf(kv.y - __uint_as_float(hi.y)),
                                  f2tf(kv.z - __uint_as_float(hi.z)),
                                  f2tf(kv.w - __uint_as_float(hi.w)));
            *(uint4*)&Kh[row * SD + c4] = hi;
            *(uint4*)&Kl[row * SD + c4] = lo;
            float4 vv = *(const float4*)(vp + (s0 + row) * 64 + c4);
            uint4 vt = make_uint4(f2tf(vv.x), f2tf(vv.y), f2tf(vv.z), f2tf(vv.w));
            *(uint4*)&Vt[row * SDV + c4] = vt;
        }
        __syncthreads();

        // ---- S = Q K^T (warp: 16q x 32s), 3x tf32 ----
        float sacc[4][4];
#pragma unroll
        for (int nt = 0; nt < 4; nt++)
#pragma unroll
            for (int i = 0; i < 4; i++) sacc[nt][i] = 0.f;
#pragma unroll
        for (int kk = 0; kk < 8; kk++) {
            int kb = kk * 8;
            uint32_t ah[4], al[4];
            const uint32_t* aph = &Qh[(qw + gid) * SD + kb + tig];
            const uint32_t* apl = &Ql[(qw + gid) * SD + kb + tig];
            ah[0] = aph[0]; ah[1] = aph[8 * SD]; ah[2] = aph[4]; ah[3] = aph[8 * SD + 4];
            al[0] = apl[0]; al[1] = apl[8 * SD]; al[2] = apl[4]; al[3] = apl[8 * SD + 4];
#pragma unroll
            for (int nt = 0; nt < 4; nt++) {
                int n0 = sb + nt * 8;
                const uint32_t* bph = &Kh[(n0 + gid) * SD + kb + tig];
                const uint32_t* bpl = &Kl[(n0 + gid) * SD + kb + tig];
                uint32_t bh0 = bph[0], bh1 = bph[4];
                uint32_t bl0 = bpl[0], bl1 = bpl[4];
#define MMA_S(Areg, B0, B1)                                                   \
    asm volatile(                                                             \
        "mma.sync.aligned.m16n8k8.row.col.f32.tf32.tf32.f32 "                 \
        "{%0,%1,%2,%3}, {%4,%5,%6,%7}, {%8,%9}, {%0,%1,%2,%3};"               \
        : "+f"(sacc[nt][0]), "+f"(sacc[nt][1]), "+f"(sacc[nt][2]),            \
          "+f"(sacc[nt][3])                                                   \
        : "r"(Areg[0]), "r"(Areg[1]), "r"(Areg[2]), "r"(Areg[3]), "r"(B0),    \
          "r"(B1));
                MMA_S(ah, bh0, bh1)
                MMA_S(ah, bl0, bl1)
                MMA_S(al, bh0, bh1)
#undef MMA_S
            }
        }

        // ---- mask + row max ----
        float mt0 = NEG_INF, mt1 = NEG_INF;
#pragma unroll
        for (int nt = 0; nt < 4; nt++) {
            int cbase = s0 + sb + nt * 8 + 2 * tig;
            sacc[nt][0] = (cbase <= row0) ? sacc[nt][0] : NEG_INF;
            sacc[nt][1] = (cbase + 1 <= row0) ? sacc[nt][1] : NEG_INF;
            sacc[nt][2] = (cbase <= row1) ? sacc[nt][2] : NEG_INF;
            sacc[nt][3] = (cbase + 1 <= row1) ? sacc[nt][3] : NEG_INF;
            mt0 = fmaxf(mt0, fmaxf(sacc[nt][0], sacc[nt][1]));
            mt1 = fmaxf(mt1, fmaxf(sacc[nt][2], sacc[nt][3]));
        }
        mt0 = fmaxf(mt0, __shfl_xor_sync(0xffffffffu, mt0, 1));
        mt0 = fmaxf(mt0, __shfl_xor_sync(0xffffffffu, mt0, 2));
        mt1 = fmaxf(mt1, __shfl_xor_sync(0xffffffffu, mt1, 1));
        mt1 = fmaxf(mt1, __shfl_xor_sync(0xffffffffu, mt1, 2));
        if (tig == 0) {
            red[sh * 64 + qw + gid] = mt0;
            red[sh * 64 + qw + gid + 8] = mt1;
        }
        __syncthreads();
        float mn0 = fmaxf(m0, fmaxf(red[qw + gid], red[64 + qw + gid]));
        float mn1 = fmaxf(m1, fmaxf(red[qw + gid + 8], red[64 + qw + gid + 8]));
        float corr0 = __expf(m0 - mn0);
        float corr1 = __expf(m1 - mn1);
        m0 = mn0; m1 = mn1;

        // ---- exp, P store, row sums ----
        float ls0 = 0.f, ls1 = 0.f;
#pragma unroll
        for (int nt = 0; nt < 4; nt++) {
            int cb = sb + nt * 8 + 2 * tig;
            float p0 = __expf(sacc[nt][0] - mn0);
            float p1 = __expf(sacc[nt][1] - mn0);
            float p2 = __expf(sacc[nt][2] - mn1);
            float p3 = __expf(sacc[nt][3] - mn1);
            ls0 += p0 + p1;
            ls1 += p2 + p3;
            Pt[(qw + gid) * SD + cb] = f2tf(p0);
            Pt[(qw + gid) * SD + cb + 1] = f2tf(p1);
            Pt[(qw + gid + 8) * SD + cb] = f2tf(p2);
            Pt[(qw + gid + 8) * SD + cb + 1] = f2tf(p3);
        }
        ls0 += __shfl_xor_sync(0xffffffffu, ls0, 1);
        ls0 += __shfl_xor_sync(0xffffffffu, ls0, 2);
        ls1 += __shfl_xor_sync(0xffffffffu, ls1, 1);
        ls1 += __shfl_xor_sync(0xffffffffu, ls1, 2);
        if (tig == 0) {
            red[128 + sh * 64 + qw + gid] = ls0;
            red[128 + sh * 64 + qw + gid + 8] = ls1;
        }
        __syncthreads();
        l0 = l0 * corr0 + red[128 + qw + gid] + red[128 + 64 + qw + gid];
        l1 = l1 * corr1 + red[128 + qw + gid + 8] + red[128 + 64 + qw + gid + 8];

        // ---- rescale O and accumulate P V (warp: 16q x 32d) ----
#pragma unroll
        for (int nt = 0; nt < 4; nt++) {
            oacc[nt][0] *= corr0;
            oacc[nt][1] *= corr0;
            oacc[nt][2] *= corr1;
            oacc[nt][3] *= corr1;
        }
#pragma unroll
        for (int kk = 0; kk < 8; kk++) {
            int kb = kk * 8;
            uint32_t af[4];
            const uint32_t* ap = &Pt[(qw + gid) * SD + kb + tig];
            af[0] = ap[0]; af[1] = ap[8 * SD]; af[2] = ap[4]; af[3] = ap[8 * SD + 4];
#pragma unroll
            for (int nt = 0; nt < 4; nt++) {
                int n0 = sb + nt * 8;
                uint32_t b0 = Vt[(kb + tig) * SDV + n0 + gid];
                uint32_t b1 = Vt[(kb + tig + 4) * SDV + n0 + gid];
                asm volatile(
                    "mma.sync.aligned.m16n8k8.row.col.f32.tf32.tf32.f32 "
                    "{%0,%1,%2,%3}, {%4,%5,%6,%7}, {%8,%9}, {%0,%1,%2,%3};"
                    : "+f"(oacc[nt][0]), "+f"(oacc[nt][1]), "+f"(oacc[nt][2]),
                      "+f"(oacc[nt][3])
                    : "r"(af[0]), "r"(af[1]), "r"(af[2]), "r"(af[3]),
                      "r"(b0), "r"(b1));
            }
        }
    }

    float inv0 = 1.f / l0, inv1 = 1.f / l1;
#pragma unroll
    for (int nt = 0; nt < 4; nt++) {
        int col = h * 64 + sb + nt * 8 + 2 * tig;
        *(float2*)&s_o[(size_t)(b * Tt + row0) * Cc + col] =
            make_float2(oacc[nt][0] * inv0, oacc[nt][1] * inv0);
        *(float2*)&s_o[(size_t)(b * Tt + row1) * Cc + col] =
            make_float2(oacc[nt][2] * inv1, oacc[nt][3] * inv1);
    }
}

// ---------------- K7: LayerNorm on o ----------------
__global__ __launch_bounds__(256) void k_lnout(const float* __restrict__ gx,
                                               const float* __restrict__ bx) {
    int bt = blockIdx.x;
    __shared__ float srow[Cc];
    __shared__ float red[16];
    float ls = 0.f, lq = 0.f;
    for (int c = threadIdx.x; c < Cc; c += 256) {
        float v = s_o[bt * Cc + c];
        srow[c] = v;
        ls += v;
        lq += v * v;
    }
#pragma unroll
    for (int o = 16; o; o >>= 1) {
        ls += __shfl_xor_sync(0xffffffffu, ls, o);
        lq += __shfl_xor_sync(0xffffffffu, lq, o);
    }
    if ((threadIdx.x & 31) == 0) {
        red[threadIdx.x >> 5] = ls;
        red[8 + (threadIdx.x >> 5)] = lq;
    }
    __syncthreads();
    float sum = 0.f, sq = 0.f;
#pragma unroll
    for (int i = 0; i < 8; i++) {
        sum += red[i];
        sq += red[8 + i];
    }
    float mu = sum * (1.f / Cc);
    float var = sq * (1.f / Cc) - mu * mu;
    float rstd = rsqrtf(var + 1e-5f);
    for (int c = threadIdx.x; c < Cc; c += 256)
        s_oln[bt * Cc + c] = (srow[c] - mu) * rstd * gx[c] + bx[c];
}

// ---------------- launch ----------------
extern "C" void kernel_launch(void* const* d_in, const int* in_sizes, int n_in,
                              void* d_out, int out_size) {
    const float* x = (const float*)d_in[0];
    const float* shift = (const float*)d_in[1];
    const float* tmx = (const float*)d_in[2];
    const float* tmr = (const float*)d_in[3];
    const float* tmk = (const float*)d_in[4];
    const float* tmv = (const float*)d_in[5];
    const float* w1 = (const float*)d_in[6];
    const float* w2 = (const float*)d_in[7];
    const float* Wq = (const float*)d_in[8];
    const float* Wk = (const float*)d_in[9];
    const float* Wv = (const float*)d_in[10];
    const float* Wo = (const float*)d_in[11];
    const float* gr = (const float*)d_in[12];
    const float* br = (const float*)d_in[13];
    const float* gk = (const float*)d_in[14];
    const float* bk = (const float*)d_in[15];
    const float* gv = (const float*)d_in[16];
    const float* bv = (const float*)d_in[17];
    const float* gx = (const float*)d_in[18];
    const float* bx = (const float*)d_in[19];
    const float* cosp = (const float*)d_in[20];
    const float* sinp = (const float*)d_in[21];
    float* out = (float*)d_out;

    cudaFuncSetAttribute(k_gemm_qkv, cudaFuncAttributeMaxDynamicSharedMemorySize, GEMM_SMEM);
    cudaFuncSetAttribute(k_gemm_out, cudaFuncAttributeMaxDynamicSharedMemorySize, GEMM_SMEM);
    cudaFuncSetAttribute(k_flash, cudaFuncAttributeMaxDynamicSharedMemorySize, FL_SMEM);

    k_shift<<<BTC / 256, 256>>>(x, shift, tmx);
    k_lora1<<<BT / 4, 96>>>(w1);
    k_mix<<<BT / 4, 256>>>(x, tmr, tmk, tmv, w2);
    k_gemm_qkv<<<dim3(16, 16, 3), 256, GEMM_SMEM>>>(Wq, Wk, Wv);
    k_lnrope<<<dim3(BT, 3), 256>>>(gr, br, gk, bk, gv, bv, cosp, sinp);
    k_flash<<<dim3(16, 64), 256, FL_SMEM>>>();
    k_lnout<<<BT, 256>>>(gx, bx);
    k_gemm_out<<<dim3(16, 16), 256, GEMM_SMEM>>>(Wo, out);
}